// round 7
// baseline (speedup 1.0000x reference)
#include <cuda_runtime.h>

#define NN     10000
#define EE     320000
#define FINN   5
#define FOUT   64
#define MLPH   32
#define CC     27
#define HIDD   450
#define FINAL  128
#define SDIM   168
#define VLEN   (NN*CC)
#define DEGCAP 96

static __device__ int    g_deg[NN];
static __device__ int    g_off[NN + 1];
static __device__ int    g_rank[EE];
static __device__ int    g_esrc[EE];
static __device__ float2 g_eea[EE];
static __device__ float  g_S[NN * SDIM];
static __device__ float  g_xl[NN * CC];
static __device__ float  g_asrc[NN];
static __device__ float  g_adst[NN];
static __device__ int    g_nnz;
static __device__ int    g_cidx[VLEN];
static __device__ float  g_cval[VLEN];
static __device__ float  g_hid[HIDD];

__global__ void k_init() {
    int i = blockIdx.x * blockDim.x + threadIdx.x;
    if (i < NN) g_deg[i] = 0;
    if (i < HIDD) g_hid[i] = 0.f;
    if (i == 0) g_nnz = 0;
}

__global__ void k_hist(const int* __restrict__ ei) {
    int e = blockIdx.x * blockDim.x + threadIdx.x;
    if (e < EE) g_rank[e] = atomicAdd(&g_deg[__ldg(&ei[EE + e])], 1);
}

// scan via smem: coalesced global in/out, serial work on LDS
__global__ void k_scan() {
    __shared__ int sdeg[10240];
    __shared__ int wsum[8];
    __shared__ int woff[8];
    int tid = threadIdx.x;
    for (int i = tid; i < 10240; i += 256) sdeg[i] = (i < NN) ? g_deg[i] : 0;
    __syncthreads();
    int start = tid * 40;
    int local = 0;
#pragma unroll 8
    for (int i = 0; i < 40; i++) local += sdeg[start + i];
    int lane = tid & 31, w = tid >> 5;
    int incl = local;
    for (int s = 1; s < 32; s <<= 1) {
        int t = __shfl_up_sync(0xffffffffu, incl, s);
        if (lane >= s) incl += t;
    }
    if (lane == 31) wsum[w] = incl;
    __syncthreads();
    if (tid == 0) {
        int c = 0;
        for (int i = 0; i < 8; i++) { woff[i] = c; c += wsum[i]; }
    }
    __syncthreads();
    int run = incl - local + woff[w];
#pragma unroll 8
    for (int i = 0; i < 40; i++) {
        int t = sdeg[start + i];
        sdeg[start + i] = run;
        run += t;
    }
    __syncthreads();
    for (int i = tid; i < NN; i += 256) g_off[i] = sdeg[i];
    if (tid == 0) g_off[NN] = EE;
}

__global__ void k_scatter(const int* __restrict__ ei, const float* __restrict__ ea) {
    int e = blockIdx.x * blockDim.x + threadIdx.x;
    if (e >= EE) return;
    int dst = __ldg(&ei[EE + e]);
    int slot = g_off[dst] + g_rank[e];
    g_esrc[slot] = __ldg(&ei[e]);
    g_eea[slot] = __ldg((const float2*)ea + e);
}

__global__ void k_S(const float* __restrict__ x, const float* __restrict__ w1,
                    const float* __restrict__ b1) {
    __shared__ float w1s[2 * MLPH];
    __shared__ float b1s[MLPH];
    int tid = threadIdx.x;
    if (tid < 2 * MLPH) w1s[tid] = w1[tid];
    if (tid < MLPH)     b1s[tid] = b1[tid];
    __syncthreads();

    int n = blockIdx.x * 8 + (tid >> 5);
    int j = tid & 31;
    float wa = w1s[j], wb = w1s[MLPH + j], bb = b1s[j];

    float s0 = 0.f, s1 = 0.f, s2 = 0.f, s3 = 0.f, s4 = 0.f, xs = 0.f;
    int k0 = g_off[n], k1 = g_off[n + 1];
#pragma unroll 2
    for (int k = k0; k < k1; k++) {
        int src = __ldg(&g_esrc[k]);
        float2 eav = __ldg(&g_eea[k]);
        float h = fmaxf(fmaf(eav.x, wa, fmaf(eav.y, wb, bb)), 0.f);
        const float* xp = x + src * FINN;
        float x0 = __ldg(xp), x1v = __ldg(xp + 1), x2v = __ldg(xp + 2),
              x3v = __ldg(xp + 3), x4v = __ldg(xp + 4);
        s0 = fmaf(h, x0, s0); s1 = fmaf(h, x1v, s1); s2 = fmaf(h, x2v, s2);
        s3 = fmaf(h, x3v, s3); s4 = fmaf(h, x4v, s4);
        if (j < FINN) {
            float xv = (j == 0) ? x0 : (j == 1) ? x1v : (j == 2) ? x2v : (j == 3) ? x3v : x4v;
            xs += xv;
        }
    }
    float* Sp = g_S + n * SDIM + j * 5;
    Sp[0] = s0; Sp[1] = s1; Sp[2] = s2; Sp[3] = s3; Sp[4] = s4;
    if (j < FINN) g_S[n * SDIM + 160 + j] = xs;
}

// NNConv epilogue + GAT linear: 4 nodes/warp, S rows staged in smem,
// weight LDGs amortized 4x (was the biggest LSU consumer at ~23us).
__global__ void k_x1xl(const float* __restrict__ x, const float* __restrict__ w2,
                       const float* __restrict__ b2, const float* __restrict__ root,
                       const float* __restrict__ nbias, const float* __restrict__ gw,
                       const float* __restrict__ asv, const float* __restrict__ adv) {
    __shared__ float sS[32][168];
    __shared__ float x1s[32][FOUT];
    __shared__ float gws[FOUT * CC];
    __shared__ float avs[CC], avd[CC];
    int tid = threadIdx.x;
    int nb = blockIdx.x * 32;

    for (int idx = tid; idx < 32 * 165; idx += 256) {
        int node = idx / 165, i = idx - node * 165;
        int n = nb + node;
        sS[node][i] = (n < NN) ? g_S[n * SDIM + i] : 0.f;
    }
    for (int i = tid; i < FOUT * CC; i += 256) gws[i] = __ldg(&gw[i]);
    if (tid < CC) { avs[tid] = __ldg(&asv[tid]); avd[tid] = __ldg(&adv[tid]); }
    __syncthreads();

    int w = tid >> 5, lane = tid & 31;
    int n0 = nb + w * 4;
    int o0 = lane, o1 = lane + 32;
    float nb0 = __ldg(&nbias[o0]), nb1 = __ldg(&nbias[o1]);
    float a0[4], a1[4];
#pragma unroll
    for (int p = 0; p < 4; p++) { a0[p] = nb0; a1[p] = nb1; }

#pragma unroll
    for (int i = 0; i < FINN; i++) {
        float r0 = __ldg(&root[i * FOUT + o0]);
        float r1 = __ldg(&root[i * FOUT + o1]);
#pragma unroll
        for (int p = 0; p < 4; p++) {
            int n = n0 + p;
            float xi = (n < NN) ? __ldg(&x[n * FINN + i]) : 0.f;
            a0[p] = fmaf(xi, r0, a0[p]);
            a1[p] = fmaf(xi, r1, a1[p]);
        }
    }
#pragma unroll 2
    for (int j = 0; j < MLPH; j++) {
#pragma unroll
        for (int i = 0; i < FINN; i++) {
            float w20 = __ldg(&w2[j * 320 + i * 64 + o0]);
            float w21 = __ldg(&w2[j * 320 + i * 64 + o1]);
#pragma unroll
            for (int p = 0; p < 4; p++) {
                float sv = sS[w * 4 + p][j * 5 + i];
                a0[p] = fmaf(sv, w20, a0[p]);
                a1[p] = fmaf(sv, w21, a1[p]);
            }
        }
    }
#pragma unroll
    for (int i = 0; i < FINN; i++) {
        float b20 = __ldg(&b2[i * 64 + o0]);
        float b21 = __ldg(&b2[i * 64 + o1]);
#pragma unroll
        for (int p = 0; p < 4; p++) {
            float sv = sS[w * 4 + p][160 + i];
            a0[p] = fmaf(sv, b20, a0[p]);
            a1[p] = fmaf(sv, b21, a1[p]);
        }
    }
#pragma unroll
    for (int p = 0; p < 4; p++) {
        x1s[w * 4 + p][o0] = fmaxf(a0[p], 0.f);
        x1s[w * 4 + p][o1] = fmaxf(a1[p], 0.f);
    }
    __syncwarp();

    int c = lane;
#pragma unroll
    for (int p = 0; p < 4; p++) {
        int n = n0 + p;
        if (n >= NN) break;               // warp-uniform
        float acc = 0.f;
        if (c < CC) {
#pragma unroll 8
            for (int o = 0; o < FOUT; o++)
                acc = fmaf(x1s[w * 4 + p][o], gws[o * CC + c], acc);
            g_xl[n * CC + c] = acc;
        }
        float vs = (c < CC) ? acc * avs[c] : 0.f;
        float vd = (c < CC) ? acc * avd[c] : 0.f;
        for (int s = 16; s; s >>= 1) {
            vs += __shfl_xor_sync(0xffffffffu, vs, s);
            vd += __shfl_xor_sync(0xffffffffu, vd, s);
        }
        if (lane == 0) { g_asrc[n] = vs; g_adst[n] = vd; }
    }
}

__device__ __forceinline__ float lrelu(float a) { return a > 0.f ? a : 0.2f * a; }

__global__ void k_gat(const float* __restrict__ gbias) {
    __shared__ float abuf[8][DEGCAP];
    __shared__ int   sbuf[8][DEGCAP];
    int w = threadIdx.x >> 5, lane = threadIdx.x & 31;
    int n = blockIdx.x * 8 + w;
    int k0 = g_off[n], k1 = g_off[n + 1];
    int deg = k1 - k0;
    bool fits = (deg <= DEGCAP);
    float ad = g_adst[n];
    float aself = lrelu(g_asrc[n] + ad);

    float m = -1e30f, d = 0.f;
    for (int k = k0 + lane; k < k1; k += 32) {
        int s = __ldg(&g_esrc[k]);
        float a = lrelu(__ldg(&g_asrc[s]) + ad);
        if (fits) { abuf[w][k - k0] = a; sbuf[w][k - k0] = s; }
        float mn = fmaxf(m, a);
        d = fmaf(d, __expf(m - mn), __expf(a - mn));
        m = mn;
    }
    for (int s = 16; s; s >>= 1) {
        float m2 = __shfl_xor_sync(0xffffffffu, m, s);
        float d2 = __shfl_xor_sync(0xffffffffu, d, s);
        float mn = fmaxf(m, m2);
        d = fmaf(d, __expf(m - mn), d2 * __expf(m2 - mn));
        m = mn;
    }
    {
        float mn = fmaxf(m, aself);
        d = fmaf(d, __expf(m - mn), __expf(aself - mn));
        m = mn;
    }
    float inv = 1.f / d;

    int c = lane;
    float out = (c < CC) ? __expf(aself - m) * inv * __ldg(&g_xl[n * CC + c]) : 0.f;
    __syncwarp();

    if (fits) {
#pragma unroll 4
        for (int i = 0; i < deg; i++) {
            float wv = __expf(abuf[w][i] - m) * inv;
            int si = sbuf[w][i];
            if (c < CC) out = fmaf(wv, __ldg(&g_xl[si * CC + c]), out);
        }
    } else {
        for (int k = k0; k < k1; k++) {
            int s = __ldg(&g_esrc[k]);
            float wv = __expf(lrelu(__ldg(&g_asrc[s]) + ad) - m) * inv;
            if (c < CC) out = fmaf(wv, __ldg(&g_xl[s * CC + c]), out);
        }
    }

    float r = 0.f;
    bool pred = false;
    if (c < CC) {
        r = out + __ldg(&gbias[c]);
        pred = (r > 0.f);
    }
    unsigned mask = __ballot_sync(0xffffffffu, pred);
    int cnt = __popc(mask);
    if (cnt) {
        int leader = __ffs(mask) - 1;
        int base = 0;
        if (lane == leader) base = atomicAdd(&g_nnz, cnt);
        base = __shfl_sync(0xffffffffu, base, leader);
        if (pred) {
            int off = __popc(mask & ((1u << lane) - 1));
            g_cidx[base + off] = n * CC + c;
            g_cval[base + off] = r;
        }
    }
}

// fc1: compacted rows, float2 columns (rows 1800B = 8B-aligned), 8-row unroll
__global__ void k_fc1(const float* __restrict__ w) {
    int t = threadIdx.x;
    if (t >= 225) return;
    int nnz = g_nnz;
    int per = (nnz + gridDim.x - 1) / gridDim.x;
    int i0 = blockIdx.x * per;
    int i1 = i0 + per; if (i1 > nnz) i1 = nnz;
    float ax = 0.f, ay = 0.f;
    int i = i0;
    for (; i + 8 <= i1; i += 8) {
#pragma unroll
        for (int u = 0; u < 8; u++) {
            int r = __ldg(&g_cidx[i + u]);
            float v = __ldg(&g_cval[i + u]);
            float2 b = __ldg((const float2*)(w + (size_t)r * HIDD) + t);
            ax = fmaf(v, b.x, ax); ay = fmaf(v, b.y, ay);
        }
    }
    for (; i < i1; i++) {
        int r = __ldg(&g_cidx[i]);
        float v = __ldg(&g_cval[i]);
        float2 b = __ldg((const float2*)(w + (size_t)r * HIDD) + t);
        ax = fmaf(v, b.x, ax); ay = fmaf(v, b.y, ay);
    }
    atomicAdd(&g_hid[2 * t], ax);
    atomicAdd(&g_hid[2 * t + 1], ay);
}

__global__ void k_fc2out(const float* __restrict__ b1v, const float* __restrict__ w2,
                         const float* __restrict__ b2v, float* __restrict__ out) {
    __shared__ float hs[HIDD];
    int t = threadIdx.x;
    for (int i = t; i < HIDD; i += 256) {
        float h = g_hid[i] + __ldg(&b1v[i]);
        hs[i] = h > 0.f ? h : 0.f;
    }
    __syncthreads();
    if (t < FINAL) {
        float a0 = 0.f, a1 = 0.f;
        // HIDD = 450 even: pair loop covers all rows, no tail
#pragma unroll 5
        for (int h = 0; h < HIDD; h += 2) {
            a0 = fmaf(hs[h],     __ldg(&w2[h * FINAL + t]),       a0);
            a1 = fmaf(hs[h + 1], __ldg(&w2[(h + 1) * FINAL + t]), a1);
        }
        float v = a0 + a1 + __ldg(&b2v[t]);
        out[t] = v > 0.f ? v : 0.f;
    }
}

extern "C" void kernel_launch(void* const* d_in, const int* in_sizes, int n_in,
                              void* d_out, int out_size) {
    const float* x        = (const float*)d_in[0];
    const int*   ei       = (const int*)  d_in[1];
    const float* ea       = (const float*)d_in[2];
    const float* mlp_w1   = (const float*)d_in[3];
    const float* mlp_b1   = (const float*)d_in[4];
    const float* mlp_w2   = (const float*)d_in[5];
    const float* mlp_b2   = (const float*)d_in[6];
    const float* nn_root  = (const float*)d_in[7];
    const float* nn_bias  = (const float*)d_in[8];
    const float* gat_w    = (const float*)d_in[9];
    const float* att_src  = (const float*)d_in[10];
    const float* att_dst  = (const float*)d_in[11];
    const float* gat_bias = (const float*)d_in[12];
    const float* fc1_w    = (const float*)d_in[13];
    const float* fc1_b    = (const float*)d_in[14];
    const float* fc2_w    = (const float*)d_in[15];
    const float* fc2_b    = (const float*)d_in[16];
    float* out = (float*)d_out;

    k_init<<<(NN + 255) / 256, 256>>>();
    k_hist<<<(EE + 255) / 256, 256>>>(ei);
    k_scan<<<1, 256>>>();
    k_scatter<<<(EE + 255) / 256, 256>>>(ei, ea);
    k_S<<<NN / 8, 256>>>(x, mlp_w1, mlp_b1);
    k_x1xl<<<(NN + 31) / 32, 256>>>(x, mlp_w2, mlp_b2, nn_root, nn_bias,
                                    gat_w, att_src, att_dst);
    k_gat<<<NN / 8, 256>>>(gat_bias);
    k_fc1<<<1024, 256>>>(fc1_w);
    k_fc2out<<<1, 256>>>(fc1_b, fc2_w, fc2_b, out);
}

// round 8
// speedup vs baseline: 1.3342x; 1.3342x over previous
#include <cuda_runtime.h>

#define NN     10000
#define EE     320000
#define FINN   5
#define FOUT   64
#define MLPH   32
#define CC     27
#define HIDD   450
#define FINAL  128
#define MLP_H  32
#define SDIM   168          // 160 (j*5+i) + 5 (x-sum for b2 term) + pad
#define VLEN   (NN*CC)      // 270000
#define MAXL   8            // max edges per lane in GAT reg cache (deg <= 256)

// ---------------- scratch (no allocations allowed) ----------------
static __device__ int   g_deg[NN];
static __device__ int   g_off[NN + 1];
static __device__ int   g_rank[EE];
static __device__ int   g_eid[EE];
static __device__ float g_S[NN * SDIM];
static __device__ float g_xl[NN * CC];
static __device__ float g_asrc[NN];
static __device__ float g_adst[NN];
static __device__ int   g_nnz;
static __device__ int   g_cidx[VLEN];
static __device__ float g_cval[VLEN];
static __device__ float g_hid[HIDD];
static __device__ float g_fin[FINAL];

// ---------------- init: zero counters/accumulators ----------------
__global__ void k_init() {
    int i = blockIdx.x * blockDim.x + threadIdx.x;
    if (i < NN) g_deg[i] = 0;
    if (i < HIDD) g_hid[i] = 0.f;
    if (i < FINAL) g_fin[i] = 0.f;
    if (i == 0) g_nnz = 0;
}

// ---------------- CSR build: histogram with per-edge rank ----------------
__global__ void k_hist(const int* __restrict__ ei) {
    int e = blockIdx.x * blockDim.x + threadIdx.x;
    if (e < EE) g_rank[e] = atomicAdd(&g_deg[ei[EE + e]], 1);
}

__global__ void k_scan() {
    const int PER = 40;                    // 256*40 = 10240 >= NN
    int tid = threadIdx.x;
    int start = tid * PER;
    int local = 0;
    for (int i = 0; i < PER; i++) {
        int idx = start + i;
        if (idx < NN) local += g_deg[idx];
    }
    int lane = tid & 31, w = tid >> 5;
    int incl = local;
    for (int s = 1; s < 32; s <<= 1) {
        int t = __shfl_up_sync(0xffffffffu, incl, s);
        if (lane >= s) incl += t;
    }
    __shared__ int wsum[8];
    __shared__ int woff[8];
    if (lane == 31) wsum[w] = incl;
    __syncthreads();
    if (tid == 0) {
        int c = 0;
        for (int i = 0; i < 8; i++) { woff[i] = c; c += wsum[i]; }
    }
    __syncthreads();
    int run = incl - local + woff[w];
    for (int i = 0; i < PER; i++) {
        int idx = start + i;
        if (idx < NN) { g_off[idx] = run; run += g_deg[idx]; }
    }
    if (tid == 0) g_off[NN] = EE;
}

// atomic-free scatter: pure permutation using precomputed ranks
__global__ void k_scatter(const int* __restrict__ ei) {
    int e = blockIdx.x * blockDim.x + threadIdx.x;
    if (e >= EE) return;
    int dst = ei[EE + e];
    g_eid[g_off[dst] + g_rank[e]] = e;
}

// ---------------- S build: warp per node, lane = j (MLP hidden idx) ----------------
__global__ void k_S(const int* __restrict__ ei, const float* __restrict__ x,
                    const float* __restrict__ ea, const float* __restrict__ w1,
                    const float* __restrict__ b1) {
    __shared__ float w1s[2 * MLP_H];
    __shared__ float b1s[MLP_H];
    int tid = threadIdx.x;
    if (tid < 2 * MLP_H) w1s[tid] = w1[tid];
    if (tid < MLP_H)     b1s[tid] = b1[tid];
    __syncthreads();

    int n = blockIdx.x * 8 + (tid >> 5);
    if (n >= NN) return;
    int j = tid & 31;
    float wa = w1s[j], wb = w1s[MLP_H + j], bb = b1s[j];

    float s0 = 0.f, s1 = 0.f, s2 = 0.f, s3 = 0.f, s4 = 0.f, xs = 0.f;
    int k0 = g_off[n], k1 = g_off[n + 1];
    for (int k = k0; k < k1; k++) {
        int e = __ldg(&g_eid[k]);
        int src = __ldg(&ei[e]);
        float e0 = __ldg(&ea[2 * e]), e1 = __ldg(&ea[2 * e + 1]);
        float h = fmaxf(fmaf(e0, wa, fmaf(e1, wb, bb)), 0.f);
        const float* xp = x + src * FINN;
        float x0 = __ldg(xp), x1v = __ldg(xp + 1), x2v = __ldg(xp + 2),
              x3v = __ldg(xp + 3), x4v = __ldg(xp + 4);
        s0 = fmaf(h, x0, s0); s1 = fmaf(h, x1v, s1); s2 = fmaf(h, x2v, s2);
        s3 = fmaf(h, x3v, s3); s4 = fmaf(h, x4v, s4);
        if (j < FINN) {
            float xv = (j == 0) ? x0 : (j == 1) ? x1v : (j == 2) ? x2v : (j == 3) ? x3v : x4v;
            xs += xv;
        }
    }
    float* Sp = g_S + n * SDIM + j * 5;
    Sp[0] = s0; Sp[1] = s1; Sp[2] = s2; Sp[3] = s3; Sp[4] = s4;
    if (j < FINN) g_S[n * SDIM + 160 + j] = xs;
}

// ---------------- fused: x1 = relu(NNConv), xl = x1@gat_w, a_src/a_dst ----------------
__global__ void k_x1xl(const float* __restrict__ x, const float* __restrict__ w2,
                       const float* __restrict__ b2, const float* __restrict__ root,
                       const float* __restrict__ nbias, const float* __restrict__ gw,
                       const float* __restrict__ asv, const float* __restrict__ adv) {
    __shared__ float x1s[8][64];
    int w = threadIdx.x >> 5, lane = threadIdx.x & 31;
    int n = blockIdx.x * 8 + w;
    if (n >= NN) return;
    const float* Sp = g_S + n * SDIM;
    int o0 = lane, o1 = lane + 32;

    float acc0 = __ldg(&nbias[o0]);
    float acc1 = __ldg(&nbias[o1]);
    const float* xp = x + n * FINN;
#pragma unroll
    for (int i = 0; i < FINN; i++) {
        float xi = __ldg(xp + i);
        acc0 = fmaf(xi, __ldg(&root[i * FOUT + o0]), acc0);
        acc1 = fmaf(xi, __ldg(&root[i * FOUT + o1]), acc1);
    }
#pragma unroll 4
    for (int j = 0; j < MLP_H; j++) {
#pragma unroll
        for (int i = 0; i < FINN; i++) {
            float sv = Sp[j * 5 + i];
            acc0 = fmaf(sv, __ldg(&w2[j * 320 + i * 64 + o0]), acc0);
            acc1 = fmaf(sv, __ldg(&w2[j * 320 + i * 64 + o1]), acc1);
        }
    }
#pragma unroll
    for (int i = 0; i < FINN; i++) {
        float sv = Sp[160 + i];
        acc0 = fmaf(sv, __ldg(&b2[i * 64 + o0]), acc0);
        acc1 = fmaf(sv, __ldg(&b2[i * 64 + o1]), acc1);
    }
    x1s[w][o0] = fmaxf(acc0, 0.f);
    x1s[w][o1] = fmaxf(acc1, 0.f);
    __syncwarp();

    int c = lane;
    float acc = 0.f;
    if (c < CC) {
#pragma unroll 8
        for (int o = 0; o < FOUT; o++)
            acc = fmaf(x1s[w][o], __ldg(&gw[o * CC + c]), acc);
        g_xl[n * CC + c] = acc;
    }
    float vs = (c < CC) ? acc * __ldg(&asv[c]) : 0.f;
    float vd = (c < CC) ? acc * __ldg(&adv[c]) : 0.f;
    for (int s = 16; s; s >>= 1) {
        vs += __shfl_xor_sync(0xffffffffu, vs, s);
        vd += __shfl_xor_sync(0xffffffffu, vd, s);
    }
    if (lane == 0) { g_asrc[n] = vs; g_adst[n] = vd; }
}

__device__ __forceinline__ float lrelu(float a) { return a > 0.f ? a : 0.2f * a; }

// ---------------- GAT: online softmax + reg-cached edges + fused compaction ----------------
__global__ void k_gat(const int* __restrict__ ei, const float* __restrict__ gbias) {
    int n = blockIdx.x * 8 + (threadIdx.x >> 5);
    if (n >= NN) return;
    int lane = threadIdx.x & 31;
    int k0 = g_off[n], k1 = g_off[n + 1];
    int deg = k1 - k0;
    float ad = g_adst[n];
    float aself = lrelu(g_asrc[n] + ad);

    // single sweep: online (max, denom); cache (a, src) per lane in regs
    float sa[MAXL]; int ss[MAXL];
    int nl = 0;
    float m = -1e30f, d = 0.f;
    for (int k = k0 + lane; k < k1; k += 32) {
        int e = __ldg(&g_eid[k]);
        int s = __ldg(&ei[e]);
        float a = lrelu(__ldg(&g_asrc[s]) + ad);
        if (nl < MAXL) { sa[nl] = a; ss[nl] = s; }
        nl++;
        float mn = fmaxf(m, a);
        d = fmaf(d, __expf(m - mn), __expf(a - mn));
        m = mn;
    }
    // combine (m,d) across lanes
    for (int s = 16; s; s >>= 1) {
        float m2 = __shfl_xor_sync(0xffffffffu, m, s);
        float d2 = __shfl_xor_sync(0xffffffffu, d, s);
        float mn = fmaxf(m, m2);
        d = fmaf(d, __expf(m - mn), d2 * __expf(m2 - mn));
        m = mn;
    }
    // self loop
    {
        float mn = fmaxf(m, aself);
        d = fmaf(d, __expf(m - mn), __expf(aself - mn));
        m = mn;
    }
    float inv = 1.f / d;

    int c = lane;
    float out = (c < CC) ? __expf(aself - m) * inv * g_xl[n * CC + c] : 0.f;

    if (deg <= 32 * MAXL) {
        int nb = (deg + 31) >> 5;
        for (int q = 0; q < nb; q++) {
            float wq = (q < nl) ? __expf(sa[q] - m) * inv : 0.f;
            int sq = (q < nl) ? ss[q] : 0;
            int cnt = min(32, deg - (q << 5));
            for (int i = 0; i < cnt; i++) {
                float wi = __shfl_sync(0xffffffffu, wq, i);
                int si = __shfl_sync(0xffffffffu, sq, i);
                if (c < CC) out = fmaf(wi, __ldg(&g_xl[si * CC + c]), out);
            }
        }
    } else {
        // fallback for pathological degree
        for (int k = k0; k < k1; k++) {
            int e = __ldg(&g_eid[k]); int s2 = __ldg(&ei[e]);
            float wv = __expf(lrelu(__ldg(&g_asrc[s2]) + ad) - m) * inv;
            if (c < CC) out = fmaf(wv, __ldg(&g_xl[s2 * CC + c]), out);
        }
    }

    // epilogue relu + warp-aggregated compaction of nonzeros
    float r = 0.f;
    bool pred = false;
    if (c < CC) {
        r = out + __ldg(&gbias[c]);
        pred = (r > 0.f);
    }
    unsigned mask = __ballot_sync(0xffffffffu, pred);
    int cnt = __popc(mask);
    if (cnt) {
        int leader = __ffs(mask) - 1;
        int base = 0;
        if (lane == leader) base = atomicAdd(&g_nnz, cnt);
        base = __shfl_sync(0xffffffffu, base, leader);
        if (pred) {
            int off = __popc(mask & ((1u << lane) - 1));
            g_cidx[base + off] = n * CC + c;
            g_cval[base + off] = r;
        }
    }
}

// ---------------- fc1: compacted-row GEMV, branchless, 4-row unroll ----------------
__global__ void k_fc1(const float* __restrict__ w) {
    int nnz = g_nnz;
    int per = (nnz + gridDim.x - 1) / gridDim.x;
    int i0 = blockIdx.x * per;
    int i1 = i0 + per; if (i1 > nnz) i1 = nnz;
    int t = threadIdx.x;
    float a0 = 0.f, a1 = 0.f;
    int i = i0;
    for (; i + 4 <= i1; i += 4) {
        int r0 = __ldg(&g_cidx[i]),     r1 = __ldg(&g_cidx[i + 1]);
        int r2 = __ldg(&g_cidx[i + 2]), r3 = __ldg(&g_cidx[i + 3]);
        float v0 = __ldg(&g_cval[i]),     v1 = __ldg(&g_cval[i + 1]);
        float v2 = __ldg(&g_cval[i + 2]), v3 = __ldg(&g_cval[i + 3]);
        const float* p0 = w + (size_t)r0 * HIDD;
        const float* p1 = w + (size_t)r1 * HIDD;
        const float* p2 = w + (size_t)r2 * HIDD;
        const float* p3 = w + (size_t)r3 * HIDD;
        a0 = fmaf(v0, __ldg(p0 + t), a0);
        a0 = fmaf(v1, __ldg(p1 + t), a0);
        a0 = fmaf(v2, __ldg(p2 + t), a0);
        a0 = fmaf(v3, __ldg(p3 + t), a0);
        if (t < HIDD - 256) {
            a1 = fmaf(v0, __ldg(p0 + 256 + t), a1);
            a1 = fmaf(v1, __ldg(p1 + 256 + t), a1);
            a1 = fmaf(v2, __ldg(p2 + 256 + t), a1);
            a1 = fmaf(v3, __ldg(p3 + 256 + t), a1);
        }
    }
    for (; i < i1; i++) {
        int r = __ldg(&g_cidx[i]);
        float v = __ldg(&g_cval[i]);
        const float* p = w + (size_t)r * HIDD;
        a0 = fmaf(v, __ldg(p + t), a0);
        if (t < HIDD - 256) a1 = fmaf(v, __ldg(p + 256 + t), a1);
    }
    atomicAdd(&g_hid[t], a0);
    if (t < HIDD - 256) atomicAdd(&g_hid[256 + t], a1);
}

// ---------------- fc2: 30 blocks x 15 rows, atomic partials ----------------
__global__ void k_fc2(const float* __restrict__ b1v, const float* __restrict__ w2) {
    int b = blockIdx.x;
    int t = threadIdx.x;
    float acc = 0.f;
#pragma unroll
    for (int i = 0; i < 15; i++) {
        int h = b * 15 + i;
        float hv = g_hid[h] + __ldg(&b1v[h]);
        hv = hv > 0.f ? hv : 0.f;
        acc = fmaf(hv, __ldg(&w2[h * FINAL + t]), acc);
    }
    atomicAdd(&g_fin[t], acc);
}

__global__ void k_out(const float* __restrict__ b2v, float* __restrict__ out) {
    int t = threadIdx.x;
    float v = g_fin[t] + __ldg(&b2v[t]);
    out[t] = v > 0.f ? v : 0.f;
}

// ---------------- launcher ----------------
extern "C" void kernel_launch(void* const* d_in, const int* in_sizes, int n_in,
                              void* d_out, int out_size) {
    const float* x        = (const float*)d_in[0];
    const int*   ei       = (const int*)  d_in[1];
    const float* ea       = (const float*)d_in[2];
    const float* mlp_w1   = (const float*)d_in[3];
    const float* mlp_b1   = (const float*)d_in[4];
    const float* mlp_w2   = (const float*)d_in[5];
    const float* mlp_b2   = (const float*)d_in[6];
    const float* nn_root  = (const float*)d_in[7];
    const float* nn_bias  = (const float*)d_in[8];
    const float* gat_w    = (const float*)d_in[9];
    const float* att_src  = (const float*)d_in[10];
    const float* att_dst  = (const float*)d_in[11];
    const float* gat_bias = (const float*)d_in[12];
    const float* fc1_w    = (const float*)d_in[13];
    const float* fc1_b    = (const float*)d_in[14];
    const float* fc2_w    = (const float*)d_in[15];
    const float* fc2_b    = (const float*)d_in[16];
    float* out = (float*)d_out;

    k_init<<<(NN + 255) / 256, 256>>>();
    k_hist<<<(EE + 255) / 256, 256>>>(ei);
    k_scan<<<1, 256>>>();
    k_scatter<<<(EE + 255) / 256, 256>>>(ei);
    k_S<<<(NN + 7) / 8, 256>>>(ei, x, ea, mlp_w1, mlp_b1);
    k_x1xl<<<(NN + 7) / 8, 256>>>(x, mlp_w2, mlp_b2, nn_root, nn_bias,
                                  gat_w, att_src, att_dst);
    k_gat<<<(NN + 7) / 8, 256>>>(ei, gat_bias);
    k_fc1<<<2048, 256>>>(fc1_w);
    k_fc2<<<30, 128>>>(fc1_b, fc2_w);
    k_out<<<1, 128>>>(fc2_b, out);
}